// round 14
// baseline (speedup 1.0000x reference)
#include <cuda_runtime.h>
#include <cuda_bf16.h>

// SphericalContraction (MipNeRF-360 eq. 10) + per-point 3x3 Jacobian.
//
//   m = ||p||
//   m <= 1 : out = p            J = I
//   m >  1 : s = 2/m - 1/m^2    out = s*p
//            c = 2(1-m)/m^4     J = s*I + c * p p^T
//
// Output layout (out_size = N*12 floats):
//   [0, 3N)   contracted points [N,3]
//   [3N,12N)  jacobians [N,3,3]
//
// R13 (final): champion R3 structure at minimum launch footprint.
//   - 1024 pts / 512 threads / 48 KB smem -> grid 4096, 4 blocks/SM,
//     64 warps/SM (100% occupancy).
//   - every global transaction is a lane-consecutive float4; smem strides
//     3 and 9 are coprime with 32 (conflict-free).
// Kernel is at the HBM write-stream ceiling: duration == 192 MB output /
// ~5.05 TB/s achieved write BW, invariant across all tested architectures.

#define PTS_PER_BLOCK 1024
#define THREADS 512

#define IN_F4  (3 * PTS_PER_BLOCK / 4)   // 768 float4
#define JAC_F4 (9 * PTS_PER_BLOCK / 4)   // 2304 float4

__device__ __forceinline__ void contract_sc(float x, float y, float z,
                                            float& s, float& c) {
    float m2 = fmaf(x, x, fmaf(y, y, z * z));
    bool inside = (m2 <= 1.0f);          // m <= 1  <=>  m^2 <= 1 (no NaN risk)
    float inv  = rsqrtf(m2);             // 1/m (garbage if m2==0; unused then)
    float m    = m2 * inv;               // m
    s          = inv * (2.0f - inv);     // 2/m - 1/m^2
    float inv2 = inv * inv;
    c          = 2.0f * (1.0f - m) * inv2 * inv2;  // 2(1-m)/m^4
    if (inside) { s = 1.0f; c = 0.0f; }  // out = p, J = I
}

__global__ void __launch_bounds__(THREADS)
contract_jac_smem_kernel(const float4* __restrict__ xin4,
                         float4* __restrict__ out_c4,  // 3N floats as float4
                         float4* __restrict__ out_j4)  // 9N floats as float4
{
    __shared__ float s_in[3 * PTS_PER_BLOCK];   // 12 KB (reused for out_c)
    __shared__ float s_j[9 * PTS_PER_BLOCK];    // 36 KB

    const int tid = threadIdx.x;
    const size_t base = (size_t)blockIdx.x * PTS_PER_BLOCK;

    // ---- coalesced input load: 768 float4 (1.5 / thread) ----
    const float4* src = xin4 + base * 3 / 4;
    float4* s_in4 = (float4*)s_in;
    s_in4[tid] = src[tid];
    if (tid < IN_F4 - THREADS) s_in4[THREADS + tid] = src[THREADS + tid];
    __syncthreads();

    // ---- compute 2 points per thread (q = tid, tid+512) ----
    float oc[6];
#pragma unroll
    for (int j = 0; j < 2; ++j) {
        int q = tid + THREADS * j;
        float x = s_in[3 * q + 0];     // stride 3: conflict-free
        float y = s_in[3 * q + 1];
        float z = s_in[3 * q + 2];

        float s, c;
        contract_sc(x, y, z, s, c);

        oc[3 * j + 0] = s * x;
        oc[3 * j + 1] = s * y;
        oc[3 * j + 2] = s * z;

        float cx = c * x, cy = c * y, cz = c * z;
        float* jr = &s_j[9 * q];       // stride 9: conflict-free
        jr[0] = fmaf(cx, x, s);  jr[1] = cx * y;          jr[2] = cx * z;
        jr[3] = cy * x;          jr[4] = fmaf(cy, y, s);  jr[5] = cy * z;
        jr[6] = cz * x;          jr[7] = cz * y;          jr[8] = fmaf(cz, z, s);
    }
    __syncthreads();   // all s_in reads done; s_j complete

    // ---- coalesced jacobian store: 2304 float4 (4.5 / thread) ----
    const float4* s_j4 = (const float4*)s_j;
    float4* dstj = out_j4 + base * 9 / 4;
#pragma unroll
    for (int i = 0; i < 4; ++i)
        dstj[tid + THREADS * i] = s_j4[tid + THREADS * i];
    if (tid < JAC_F4 - 4 * THREADS)
        dstj[tid + THREADS * 4] = s_j4[tid + THREADS * 4];

    // ---- stage contracted points into s_in (safe: reads finished) ----
#pragma unroll
    for (int j = 0; j < 2; ++j) {
        int q = tid + THREADS * j;
        s_in[3 * q + 0] = oc[3 * j + 0];
        s_in[3 * q + 1] = oc[3 * j + 1];
        s_in[3 * q + 2] = oc[3 * j + 2];
    }
    __syncthreads();

    // ---- coalesced contracted store: 768 float4 ----
    float4* dstc = out_c4 + base * 3 / 4;
    dstc[tid] = s_in4[tid];
    if (tid < IN_F4 - THREADS) dstc[THREADS + tid] = s_in4[THREADS + tid];
}

// Scalar tail / contract-only fallback.
__global__ void contract_jac_tail_kernel(const float* __restrict__ xin,
                                         float* __restrict__ out_c,
                                         float* __restrict__ out_j,  // may be null
                                         int start, int n) {
    int i = start + blockIdx.x * blockDim.x + threadIdx.x;
    if (i >= n) return;
    float x = xin[3 * i], y = xin[3 * i + 1], z = xin[3 * i + 2];
    float s, c;
    contract_sc(x, y, z, s, c);
    out_c[3 * i + 0] = s * x;
    out_c[3 * i + 1] = s * y;
    out_c[3 * i + 2] = s * z;
    if (out_j) {
        float cx = c * x, cy = c * y, cz = c * z;
        float* jr = &out_j[9 * (size_t)i];
        jr[0] = fmaf(cx, x, s);  jr[1] = cx * y;          jr[2] = cx * z;
        jr[3] = cy * x;          jr[4] = fmaf(cy, y, s);  jr[5] = cy * z;
        jr[6] = cz * x;          jr[7] = cz * y;          jr[8] = fmaf(cz, z, s);
    }
}

extern "C" void kernel_launch(void* const* d_in, const int* in_sizes, int n_in,
                              void* d_out, int out_size) {
    const float* x = (const float*)d_in[0];
    int n = in_sizes[0] / 3;                 // number of points
    float* out_c = (float*)d_out;
    bool want_jac = (out_size >= 12 * n);
    float* out_j = want_jac ? out_c + 3 * (size_t)n : nullptr;

    if (want_jac) {
        int nfull = n / PTS_PER_BLOCK;
        if (nfull > 0) {
            contract_jac_smem_kernel<<<nfull, THREADS>>>(
                (const float4*)x, (float4*)out_c, (float4*)out_j);
        }
        int done = nfull * PTS_PER_BLOCK;
        if (done < n) {
            int rem = n - done;
            contract_jac_tail_kernel<<<(rem + 255) / 256, 256>>>(
                x, out_c, out_j, done, n);
        }
    } else {
        contract_jac_tail_kernel<<<(n + 255) / 256, 256>>>(
            x, out_c, nullptr, 0, n);
    }
}

// round 15
// speedup vs baseline: 1.0327x; 1.0327x over previous
#include <cuda_runtime.h>
#include <cuda_bf16.h>

// SphericalContraction (MipNeRF-360 eq. 10) + per-point 3x3 Jacobian.
//
//   m = ||p||
//   m <= 1 : out = p            J = I
//   m >  1 : s = 2/m - 1/m^2    out = s*p
//            c = 2(1-m)/m^4     J = s*I + c * p p^T
//
// Output layout (out_size = N*12 floats):
//   [0, 3N)   contracted points [N,3]
//   [3N,12N)  jacobians [N,3,3]
//
// FINAL (champion, R3 configuration — best measured dur_us 41.4).
// The kernel is at the HBM write-stream ceiling: duration == 192 MB output
// / ~5.05 TB/s achieved write BW, invariant across every tested
// architecture (STG.128, scalar+hints, TMA bulk, persistent pipeline,
// write-through). Structure:
//   - 512 pts / 256 threads / 24 KB smem -> 8 blocks/SM (full warp cap)
//   - every global transaction is a lane-consecutive float4 (zero L1
//     wavefront amplification)
//   - smem strides 3 and 9 are coprime with 32 (bank-conflict-free)

#define PTS_PER_BLOCK 512
#define THREADS 256

__device__ __forceinline__ void contract_sc(float x, float y, float z,
                                            float& s, float& c) {
    float m2 = fmaf(x, x, fmaf(y, y, z * z));
    bool inside = (m2 <= 1.0f);          // m <= 1  <=>  m^2 <= 1 (no NaN risk)
    float inv  = rsqrtf(m2);             // 1/m (garbage if m2==0; unused then)
    float m    = m2 * inv;               // m
    s          = inv * (2.0f - inv);     // 2/m - 1/m^2
    float inv2 = inv * inv;
    c          = 2.0f * (1.0f - m) * inv2 * inv2;  // 2(1-m)/m^4
    if (inside) { s = 1.0f; c = 0.0f; }  // out = p, J = I
}

__global__ void __launch_bounds__(THREADS)
contract_jac_smem_kernel(const float4* __restrict__ xin4,
                         float4* __restrict__ out_c4,  // 3N floats as float4
                         float4* __restrict__ out_j4)  // 9N floats as float4
{
    __shared__ float s_in[3 * PTS_PER_BLOCK];   // 6 KB (reused for out_c)
    __shared__ float s_j[9 * PTS_PER_BLOCK];    // 18 KB

    const int tid = threadIdx.x;
    const size_t base = (size_t)blockIdx.x * PTS_PER_BLOCK;

    // ---- coalesced input load: 3*512 floats = 384 float4 ----
    const float4* src = xin4 + base * 3 / 4;
    float4* s_in4 = (float4*)s_in;
    s_in4[tid] = src[tid];
    if (tid < 128) s_in4[256 + tid] = src[256 + tid];
    __syncthreads();

    // ---- compute 2 points per thread (q = tid, tid+256) ----
    float oc[6];
#pragma unroll
    for (int j = 0; j < 2; ++j) {
        int q = tid + THREADS * j;
        float x = s_in[3 * q + 0];     // stride 3: conflict-free
        float y = s_in[3 * q + 1];
        float z = s_in[3 * q + 2];

        float s, c;
        contract_sc(x, y, z, s, c);

        oc[3 * j + 0] = s * x;
        oc[3 * j + 1] = s * y;
        oc[3 * j + 2] = s * z;

        float cx = c * x, cy = c * y, cz = c * z;
        float* jr = &s_j[9 * q];       // stride 9: conflict-free
        jr[0] = fmaf(cx, x, s);  jr[1] = cx * y;          jr[2] = cx * z;
        jr[3] = cy * x;          jr[4] = fmaf(cy, y, s);  jr[5] = cy * z;
        jr[6] = cz * x;          jr[7] = cz * y;          jr[8] = fmaf(cz, z, s);
    }
    __syncthreads();   // all s_in reads done; s_j complete

    // ---- coalesced jacobian store: 9*512 floats = 1152 float4 ----
    const float4* s_j4 = (const float4*)s_j;
    float4* dstj = out_j4 + base * 9 / 4;
#pragma unroll
    for (int i = 0; i < 4; ++i)
        dstj[tid + THREADS * i] = s_j4[tid + THREADS * i];
    if (tid < 128) dstj[tid + THREADS * 4] = s_j4[tid + THREADS * 4];

    // ---- stage contracted points into s_in (safe: reads finished) ----
#pragma unroll
    for (int j = 0; j < 2; ++j) {
        int q = tid + THREADS * j;
        s_in[3 * q + 0] = oc[3 * j + 0];
        s_in[3 * q + 1] = oc[3 * j + 1];
        s_in[3 * q + 2] = oc[3 * j + 2];
    }
    __syncthreads();

    // ---- coalesced contracted store: 384 float4 ----
    float4* dstc = out_c4 + base * 3 / 4;
    dstc[tid] = s_in4[tid];
    if (tid < 128) dstc[256 + tid] = s_in4[256 + tid];
}

// Scalar tail / contract-only fallback.
__global__ void contract_jac_tail_kernel(const float* __restrict__ xin,
                                         float* __restrict__ out_c,
                                         float* __restrict__ out_j,  // may be null
                                         int start, int n) {
    int i = start + blockIdx.x * blockDim.x + threadIdx.x;
    if (i >= n) return;
    float x = xin[3 * i], y = xin[3 * i + 1], z = xin[3 * i + 2];
    float s, c;
    contract_sc(x, y, z, s, c);
    out_c[3 * i + 0] = s * x;
    out_c[3 * i + 1] = s * y;
    out_c[3 * i + 2] = s * z;
    if (out_j) {
        float cx = c * x, cy = c * y, cz = c * z;
        float* jr = &out_j[9 * (size_t)i];
        jr[0] = fmaf(cx, x, s);  jr[1] = cx * y;          jr[2] = cx * z;
        jr[3] = cy * x;          jr[4] = fmaf(cy, y, s);  jr[5] = cy * z;
        jr[6] = cz * x;          jr[7] = cz * y;          jr[8] = fmaf(cz, z, s);
    }
}

extern "C" void kernel_launch(void* const* d_in, const int* in_sizes, int n_in,
                              void* d_out, int out_size) {
    const float* x = (const float*)d_in[0];
    int n = in_sizes[0] / 3;                 // number of points
    float* out_c = (float*)d_out;
    bool want_jac = (out_size >= 12 * n);
    float* out_j = want_jac ? out_c + 3 * (size_t)n : nullptr;

    if (want_jac) {
        int nfull = n / PTS_PER_BLOCK;
        if (nfull > 0) {
            contract_jac_smem_kernel<<<nfull, THREADS>>>(
                (const float4*)x, (float4*)out_c, (float4*)out_j);
        }
        int done = nfull * PTS_PER_BLOCK;
        if (done < n) {
            int rem = n - done;
            contract_jac_tail_kernel<<<(rem + 255) / 256, 256>>>(
                x, out_c, out_j, done, n);
        }
    } else {
        contract_jac_tail_kernel<<<(n + 255) / 256, 256>>>(
            x, out_c, nullptr, 0, n);
    }
}